// round 3
// baseline (speedup 1.0000x reference)
#include <cuda_runtime.h>
#include <math.h>

#define LD 65  // padded row stride for 64x64 tiles in smem (conflict-free both axes)

// ---------------- intermediates (device globals; no allocation allowed) ---------------
__device__ float g_Mp0[64 * 64];     // (n1, n2) : feat_tra @ feat_det^T + iou
__device__ float g_m1[64 * 512];
__device__ float g_m2[64 * 512];
__device__ float g_u1[64 * 512];
__device__ float g_u2[64 * 512];
__device__ float g_e1[64 * 512];
__device__ float g_e2[64 * 512];
__device__ float g_P[64 * 64];       // P[a,b] = Mp[b,a] = e1[b] . e2[a]   (a over n2, b over n1)

__device__ __forceinline__ float warpSum(float v) {
#pragma unroll
    for (int o = 16; o; o >>= 1) v += __shfl_xor_sync(0xffffffffu, v, o);
    return v;
}
__device__ __forceinline__ float warpMax(float v) {
#pragma unroll
    for (int o = 16; o; o >>= 1) v = fmaxf(v, __shfl_xor_sync(0xffffffffu, v, o));
    return v;
}

// ---------------- Mp0 = feat_tra @ feat_det^T + iou : warp per output --------------
__global__ void k_mp0(const float* __restrict__ tra, const float* __restrict__ det,
                      const float* __restrict__ iou) {
    int g = blockIdx.x * 32 + (threadIdx.x >> 5);
    int lane = threadIdx.x & 31;
    int i = g >> 6, j = g & 63;
    const float* a = tra + i * 512;
    const float* b = det + j * 512;
    float s = 0.f;
#pragma unroll 4
    for (int k = lane; k < 512; k += 32) s += a[k] * b[k];
    s = warpSum(s);
    if (!lane) g_Mp0[i * 64 + j] = s + iou[i * 64 + j];
}

// ---------------- m1 = Mp0 @ det, m2 = Mp0^T @ tra : thread per output -------------
__global__ void k_m12(const float* __restrict__ tra, const float* __restrict__ det) {
    int t = blockIdx.x * blockDim.x + threadIdx.x;
    if (t < 32768) {
        int i = t >> 9, k = t & 511;
        float s = 0.f;
#pragma unroll 8
        for (int j = 0; j < 64; j++) s += g_Mp0[i * 64 + j] * det[j * 512 + k];
        g_m1[t] = s;
    } else {
        int t2 = t - 32768;
        int j = t2 >> 9, k = t2 & 511;
        float s = 0.f;
#pragma unroll 8
        for (int i = 0; i < 64; i++) s += g_Mp0[i * 64 + j] * tra[i * 512 + k];
        g_m2[t2] = s;
    }
}

// ---------------- u = feat + lam * m, lam = |feat| / |m| ---------------------------
__global__ void k_u(const float* __restrict__ tra, const float* __restrict__ det) {
    __shared__ float pf[16], pm[16];
    __shared__ float sLam;
    int r = blockIdx.x;
    const float* f;
    const float* m;
    float* u;
    if (r < 64) { f = tra + r * 512; m = g_m1 + r * 512; u = g_u1 + r * 512; }
    else        { r -= 64; f = det + r * 512; m = g_m2 + r * 512; u = g_u2 + r * 512; }
    int t = threadIdx.x;
    float fv = f[t], mv = m[t];
    float sf = warpSum(fv * fv);
    float sm = warpSum(mv * mv);
    int w = t >> 5, lane = t & 31;
    if (!lane) { pf[w] = sf; pm[w] = sm; }
    __syncthreads();
    if (t < 32) {
        float a = (t < 16) ? pf[t] : 0.f;
        float b = (t < 16) ? pm[t] : 0.f;
        a = warpSum(a);
        b = warpSum(b);
        if (!t) sLam = sqrtf(a) / sqrtf(b);
    }
    __syncthreads();
    u[t] = fv + sLam * mv;
}

// ---------------- e = relu(u @ W^T + b) : warp per output --------------------------
__global__ void k_egemm(const float* __restrict__ W, const float* __restrict__ bias) {
    int gw = blockIdx.x * 32 + (threadIdx.x >> 5);
    int lane = threadIdx.x & 31;
    int tensor = gw >> 15;
    int loc = gw & 32767;
    int i = loc >> 9, j = loc & 511;
    const float* u = (tensor ? g_u2 : g_u1) + i * 512;
    const float* w = W + j * 512;
    float s = 0.f;
#pragma unroll 4
    for (int k = lane; k < 512; k += 32) s += u[k] * w[k];
    s = warpSum(s);
    if (!lane) {
        float v = fmaxf(s + bias[j], 0.f);
        (tensor ? g_e2 : g_e1)[i * 512 + j] = v;
    }
}

// ---------------- row-wise L2 normalize e in place ---------------------------------
__global__ void k_enorm() {
    __shared__ float p[16];
    __shared__ float sScale;
    int r = blockIdx.x;
    float* e = (r < 64) ? (g_e1 + r * 512) : (g_e2 + (r - 64) * 512);
    int t = threadIdx.x;
    float v = e[t];
    float s = warpSum(v * v);
    if (!(t & 31)) p[t >> 5] = s;
    __syncthreads();
    if (t < 32) {
        float a = (t < 16) ? p[t] : 0.f;
        a = warpSum(a);
        if (!t) sScale = 1.f / fmaxf(sqrtf(a), 1e-12f);
    }
    __syncthreads();
    e[t] = v * sScale;
}

// ---------------- P[a,b] = e1[b] . e2[a] : warp per output --------------------------
__global__ void k_P() {
    int g = blockIdx.x * 32 + (threadIdx.x >> 5);
    int lane = threadIdx.x & 31;
    int a = g >> 6, b = g & 63;
    const float* x = g_e1 + b * 512;
    const float* y = g_e2 + a * 512;
    float s = 0.f;
#pragma unroll 4
    for (int k = lane; k < 512; k += 32) s += x[k] * y[k];
    s = warpSum(s);
    if (!lane) g_P[a * 64 + b] = s;
}

// ---------------- ADMM + PCG, everything in shared memory, one block ---------------
// K = beta*I + rho*(I(x)J + J(x)I) - 0.5*(D_p*S + S*D_p),  S = (J-I)(x)(J-I)
// Matvec:  (Kd)[a,b] = beta*d + rho*(Rd_a + Cd_b)
//                      - 0.5*( P*(Td - Rd_a - Cd_b + d) + (Te - Re_a - Ce_b + e) ),  e = P.*d
// Preconditioner B = beta*I + rho*(I(x)J + J(x)I):
//   (B^-1 r)[a,b] = r/beta + cRC*(Rr_a + Cr_b) + cT*Tr
__global__ void __launch_bounds__(1024, 1) k_admm(float* __restrict__ out) {
    extern __shared__ float sm[];
    float* X  = sm;            // 4160 each (64*65)
    float* Rr = sm + 4160;
    float* Dd = sm + 8320;
    float* Qv = sm + 12480;
    float* Z1 = sm + 16640;
    float* Y1 = sm + 20800;
    float* Pm = sm + 24960;
    float* RA  = sm + 29120;   // 64 each
    float* CA  = RA + 64;
    float* RB  = CA + 64;
    float* CB  = RB + 64;
    float* y2c = CB + 64;
    float* y2r = y2c + 64;
    float* part = y2r + 64;    // 32
    float* scal = part + 32;   // 8

    const float rho   = 100.f;
    const float sigma = 1e-3f;
    const float beta  = 3969.f + rho + sigma;        // (n1-1)(n2-1) + rho + sigma
    const float binv  = 1.f / beta;
    const float b64i  = 1.f / (beta + 64.f * rho);
    const float b128i = 1.f / (beta + 128.f * rho);
    const float cRC   = (b64i - binv) * (1.f / 64.f);
    const float cT    = (b128i - 2.f * b64i + binv) * (1.f / 4096.f);

    int tid = threadIdx.x;
    int w = tid >> 5, lane = tid & 31;
    int a0 = tid >> 6, b0 = tid & 63;
    int off[4], aa[4];
#pragma unroll
    for (int k = 0; k < 4; k++) { aa[k] = a0 + 16 * k; off[k] = aa[k] * LD + b0; }

    // init state
#pragma unroll
    for (int k = 0; k < 4; k++) {
        X[off[k]] = 0.f; Z1[off[k]] = 0.f; Y1[off[k]] = 0.f;
        Pm[off[k]] = g_P[aa[k] * 64 + b0];
    }
    if (tid < 64) { y2c[tid] = 0.f; y2r[tid] = 0.f; }
    __syncthreads();

    auto blockRed = [&](float v, int slot) {
        v = warpSum(v);
        if (!lane) part[w] = v;
        __syncthreads();
        if (w == 0) {
            float x = part[lane];
            x = warpSum(x);
            if (!lane) scal[slot] = x;
        }
        __syncthreads();
    };

    // row/col/total sums of M  -> RA, CA, scal[0]
    auto sums1 = [&](const float* M) {
#pragma unroll
        for (int rr = 0; rr < 2; rr++) {
            int r = 2 * w + rr;
            float v = M[r * LD + lane] + M[r * LD + lane + 32];
            v = warpSum(v);
            if (!lane) RA[r] = v;
            float u = M[lane * LD + r] + M[(lane + 32) * LD + r];
            u = warpSum(u);
            if (!lane) CA[r] = u;
        }
        __syncthreads();
        if (w == 0) {
            float v = warpSum(RA[lane] + RA[lane + 32]);
            if (!lane) scal[0] = v;
        }
        __syncthreads();
    };

    // sums of M (RA,CA,scal[0]) and of P.*M (RB,CB,scal[1])
    auto sums2 = [&](const float* M) {
#pragma unroll
        for (int rr = 0; rr < 2; rr++) {
            int r = 2 * w + rr;
            float m0 = M[r * LD + lane], m1v = M[r * LD + lane + 32];
            float p0 = Pm[r * LD + lane], p1 = Pm[r * LD + lane + 32];
            float va = warpSum(m0 + m1v);
            float vb = warpSum(p0 * m0 + p1 * m1v);
            if (!lane) { RA[r] = va; RB[r] = vb; }
            float c0 = M[lane * LD + r], c1 = M[(lane + 32) * LD + r];
            float q0 = Pm[lane * LD + r], q1 = Pm[(lane + 32) * LD + r];
            float ua = warpSum(c0 + c1);
            float ub = warpSum(q0 * c0 + q1 * c1);
            if (!lane) { CA[r] = ua; CB[r] = ub; }
        }
        __syncthreads();
        if (w == 0) {
            float v = warpSum(RA[lane] + RA[lane + 32]);
            if (!lane) scal[0] = v;
        } else if (w == 1) {
            float v = warpSum(RB[lane] + RB[lane + 32]);
            if (!lane) scal[1] = v;
        }
        __syncthreads();
    };

    auto applyK = [&](float d, float p, int a, int b, float TA, float TB) -> float {
        float e = p * d;
        return beta * d + rho * (RA[a] + CA[b])
             - 0.5f * (p * (TA - RA[a] - CA[b] + d) + (TB - RB[a] - CB[b] + e));
    };

    for (int it = 0; it < 150; ++it) {
        // r = rhs - K x   (warm start from previous x), also |rhs|^2
        sums2(X);
        {
            float TA = scal[0], TB = scal[1];
            float loc = 0.f;
#pragma unroll
            for (int k = 0; k < 4; k++) {
                int o = off[k], a = aa[k];
                float x = X[o], p = Pm[o];
                float kx = applyK(x, p, a, b0, TA, TB);
                float rhs = sigma * x + p + (rho * Z1[o] - Y1[o])
                          + (rho - y2c[b0]) + (rho - y2r[a]);
                Rr[o] = rhs - kx;
                loc += rhs * rhs;
            }
            blockRed(loc, 2);
        }
        float tol2 = fmaxf(scal[2] * 1e-14f, 1e-30f);

        // z0 = B^-1 r; d0 = z0; rho_s = r.z
        sums1(Rr);
        {
            float TR = scal[0];
            float loc = 0.f;
#pragma unroll
            for (int k = 0; k < 4; k++) {
                int o = off[k];
                float r = Rr[o];
                float z = binv * r + cRC * (RA[aa[k]] + CA[b0]) + cT * TR;
                Dd[o] = z;
                loc += r * z;
            }
            blockRed(loc, 3);
        }
        float rho_s = scal[3];

        if (rho_s > 0.f) {
            float prev_rn2 = 3.4e38f;
            int stagn = 0;
            for (int cg = 0; cg < 150; ++cg) {
                sums2(Dd);
                float TA = scal[0], TB = scal[1];
                float loc = 0.f;
#pragma unroll
                for (int k = 0; k < 4; k++) {
                    int o = off[k];
                    float d = Dd[o], p = Pm[o];
                    float q = applyK(d, p, aa[k], b0, TA, TB);
                    Qv[o] = q;
                    loc += d * q;
                }
                blockRed(loc, 2);
                float dq = scal[2];
                if (!(dq > 0.f)) break;
                float alpha = rho_s / dq;
                loc = 0.f;
#pragma unroll
                for (int k = 0; k < 4; k++) {
                    int o = off[k];
                    X[o] += alpha * Dd[o];
                    float r = Rr[o] - alpha * Qv[o];
                    Rr[o] = r;
                    loc += r * r;
                }
                blockRed(loc, 2);
                float rn2 = scal[2];
                if (rn2 <= tol2) break;
                if (rn2 >= 0.99f * prev_rn2) { if (++stagn >= 3) break; }
                else stagn = 0;
                prev_rn2 = rn2;

                sums1(Rr);
                float TR = scal[0];
                loc = 0.f;
#pragma unroll
                for (int k = 0; k < 4; k++) {
                    int o = off[k];
                    float r = Rr[o];
                    float z = binv * r + cRC * (RA[aa[k]] + CA[b0]) + cT * TR;
                    loc += r * z;
                }
                blockRed(loc, 3);
                float rho_n = scal[3];
                float bk = rho_n / rho_s;
                rho_s = rho_n;
#pragma unroll
                for (int k = 0; k < 4; k++) {
                    int o = off[k];
                    float r = Rr[o];
                    float z = binv * r + cRC * (RA[aa[k]] + CA[b0]) + cT * TR;
                    Dd[o] = z + bk * Dd[o];
                }
                __syncthreads();
            }
        }

        // z, y updates
        sums1(X);
#pragma unroll
        for (int k = 0; k < 4; k++) {
            int o = off[k];
            float x = X[o];
            float v = x + Y1[o] * (1.f / rho);
            float zn = fminf(fmaxf(v, 0.f), 1e6f);
            Y1[o] += rho * (x - zn);
            Z1[o] = zn;
        }
        if (tid < 64) {
            y2c[tid] += rho * (CA[tid] - 1.f);
            y2r[tid] += rho * (RA[tid] - 1.f);
        }
        __syncthreads();
    }

    // out[0][j][i] = softmax_i( 200 * clip(X[i][j], 0, 1) )  -> column-wise softmax of X
#pragma unroll
    for (int rr = 0; rr < 2; rr++) {
        int c = 2 * w + rr;
        float v1 = fminf(fmaxf(X[lane * LD + c], 0.f), 1.f);
        float v2 = fminf(fmaxf(X[(lane + 32) * LD + c], 0.f), 1.f);
        float mx = warpMax(fmaxf(v1, v2));
        float e1v = expf(200.f * (v1 - mx));
        float e2v = expf(200.f * (v2 - mx));
        float s = warpSum(e1v + e2v);
        out[c * 64 + lane] = e1v / s;
        out[c * 64 + lane + 32] = e2v / s;
    }
}

// ------------------------------------------------------------------------------------
extern "C" void kernel_launch(void* const* d_in, const int* in_sizes, int n_in,
                              void* d_out, int out_size) {
    const float* tra = (const float*)d_in[0];   // (64,512)
    const float* det = (const float*)d_in[1];   // (64,512)
    const float* iou = (const float*)d_in[2];   // (64,64)
    const float* W   = (const float*)d_in[3];   // (512,512)
    const float* b   = (const float*)d_in[4];   // (512,)
    float* out = (float*)d_out;                 // (1,64,64)

    const int SMEM_BYTES = (29120 + 6 * 64 + 32 + 8) * 4;  // 118176
    cudaFuncSetAttribute(k_admm, cudaFuncAttributeMaxDynamicSharedMemorySize, SMEM_BYTES);

    k_mp0<<<128, 1024>>>(tra, det, iou);
    k_m12<<<64, 1024>>>(tra, det);
    k_u<<<128, 512>>>(tra, det);
    k_egemm<<<2048, 1024>>>(W, b);
    k_enorm<<<128, 512>>>();
    k_P<<<128, 1024>>>();
    k_admm<<<1, 1024, SMEM_BYTES>>>(out);
}

// round 5
// speedup vs baseline: 1.2947x; 1.2947x over previous
#include <cuda_runtime.h>
#include <math.h>

#define LD 65  // padded row stride for 64x64 tiles in smem

// ---------------- intermediates (device globals; no allocation allowed) -----------
__device__ float g_Mp0[64 * 64];
__device__ float g_m1[64 * 512];
__device__ float g_m2[64 * 512];
__device__ float g_u1[64 * 512];
__device__ float g_u2[64 * 512];
__device__ float g_e1[64 * 512];
__device__ float g_e2[64 * 512];
__device__ float g_P[64 * 64];   // P[a,b] = e1[b] . e2[a]

__device__ __forceinline__ float warpSum(float v) {
#pragma unroll
    for (int o = 16; o; o >>= 1) v += __shfl_xor_sync(0xffffffffu, v, o);
    return v;
}
__device__ __forceinline__ float warpMax(float v) {
#pragma unroll
    for (int o = 16; o; o >>= 1) v = fmaxf(v, __shfl_xor_sync(0xffffffffu, v, o));
    return v;
}
// reduce within each 16-lane half of a warp (4 steps)
__device__ __forceinline__ float dual16(float v) {
#pragma unroll
    for (int o = 8; o; o >>= 1) v += __shfl_xor_sync(0xffffffffu, v, o);
    return v;
}

// ---------------- Mp0 = feat_tra @ feat_det^T + iou : warp per output -------------
__global__ void k_mp0(const float* __restrict__ tra, const float* __restrict__ det,
                      const float* __restrict__ iou) {
    int gw = blockIdx.x * 32 + (threadIdx.x >> 5);
    int lane = threadIdx.x & 31;
    int i = gw >> 6, j = gw & 63;
    const float* a = tra + i * 512;
    const float* b = det + j * 512;
    float s = 0.f;
#pragma unroll 4
    for (int k = lane; k < 512; k += 32) s += a[k] * b[k];
    s = warpSum(s);
    if (!lane) g_Mp0[i * 64 + j] = s + iou[i * 64 + j];
}

// ---------------- m1 = Mp0 @ det, m2 = Mp0^T @ tra --------------------------------
__global__ void k_m12(const float* __restrict__ tra, const float* __restrict__ det) {
    int t = blockIdx.x * blockDim.x + threadIdx.x;
    if (t < 32768) {
        int i = t >> 9, k = t & 511;
        float s = 0.f;
#pragma unroll 8
        for (int j = 0; j < 64; j++) s += g_Mp0[i * 64 + j] * det[j * 512 + k];
        g_m1[t] = s;
    } else {
        int t2 = t - 32768;
        int j = t2 >> 9, k = t2 & 511;
        float s = 0.f;
#pragma unroll 8
        for (int i = 0; i < 64; i++) s += g_Mp0[i * 64 + j] * tra[i * 512 + k];
        g_m2[t2] = s;
    }
}

// ---------------- u = feat + lam * m ----------------------------------------------
__global__ void k_u(const float* __restrict__ tra, const float* __restrict__ det) {
    __shared__ float pf[16], pm[16];
    __shared__ float sLam;
    int rr = blockIdx.x;
    const float* f;
    const float* m;
    float* u;
    if (rr < 64) { f = tra + rr * 512; m = g_m1 + rr * 512; u = g_u1 + rr * 512; }
    else         { rr -= 64; f = det + rr * 512; m = g_m2 + rr * 512; u = g_u2 + rr * 512; }
    int t = threadIdx.x;
    float fv = f[t], mv = m[t];
    float sf = warpSum(fv * fv);
    float smv = warpSum(mv * mv);
    int w = t >> 5, lane = t & 31;
    if (!lane) { pf[w] = sf; pm[w] = smv; }
    __syncthreads();
    if (t < 32) {
        float a = (t < 16) ? pf[t] : 0.f;
        float b = (t < 16) ? pm[t] : 0.f;
        a = warpSum(a);
        b = warpSum(b);
        if (!t) sLam = sqrtf(a) / sqrtf(b);
    }
    __syncthreads();
    u[t] = fv + sLam * mv;
}

// ---------------- e = relu(u @ W^T + b) : warp per output -------------------------
__global__ void k_egemm(const float* __restrict__ W, const float* __restrict__ bias) {
    int gw = blockIdx.x * 32 + (threadIdx.x >> 5);
    int lane = threadIdx.x & 31;
    int tensor = gw >> 15;
    int loc = gw & 32767;
    int i = loc >> 9, j = loc & 511;
    const float* u = (tensor ? g_u2 : g_u1) + i * 512;
    const float* wv = W + j * 512;
    float s = 0.f;
#pragma unroll 4
    for (int k = lane; k < 512; k += 32) s += u[k] * wv[k];
    s = warpSum(s);
    if (!lane) {
        float v = fmaxf(s + bias[j], 0.f);
        (tensor ? g_e2 : g_e1)[i * 512 + j] = v;
    }
}

// ---------------- row-wise L2 normalize e in place --------------------------------
__global__ void k_enorm() {
    __shared__ float pp[16];
    __shared__ float sScale;
    int rr = blockIdx.x;
    float* e = (rr < 64) ? (g_e1 + rr * 512) : (g_e2 + (rr - 64) * 512);
    int t = threadIdx.x;
    float v = e[t];
    float s = warpSum(v * v);
    if (!(t & 31)) pp[t >> 5] = s;
    __syncthreads();
    if (t < 32) {
        float a = (t < 16) ? pp[t] : 0.f;
        a = warpSum(a);
        if (!t) sScale = 1.f / fmaxf(sqrtf(a), 1e-12f);
    }
    __syncthreads();
    e[t] = v * sScale;
}

// ---------------- P[a,b] = e1[b] . e2[a] ------------------------------------------
__global__ void k_P() {
    int gw = blockIdx.x * 32 + (threadIdx.x >> 5);
    int lane = threadIdx.x & 31;
    int a = gw >> 6, b = gw & 63;
    const float* x = g_e1 + b * 512;
    const float* y = g_e2 + a * 512;
    float s = 0.f;
#pragma unroll 4
    for (int k = lane; k < 512; k += 32) s += x[k] * y[k];
    s = warpSum(s);
    if (!lane) g_P[a * 64 + b] = s;
}

// ---------------- ADMM + PCG, register state, 5 barriers / CG iter -----------------
// K = beta*I + rho*(I(x)J + J(x)I) - 0.5*(D_p*S + S*D_p),  S = (J-I)(x)(J-I)
// (Kd)[a,b] = beta*d + rho*(Rd_a + Cd_b)
//             - 0.5*( p*(Td - Rd_a - Cd_b + d) + (Te - Re_a - Ce_b + p*d) ), e = p.*d
// B = beta*I + rho*(I(x)J + J(x)I): (B^-1 r)[a,b] = binv*r + cRC*(Rr_a+Cr_b) + cT*Tr
// r.B^-1 r = binv*|r|^2 + cRC*(sum_a Rr_a^2 + sum_b Cr_b^2) + cT*Tr^2
__global__ void __launch_bounds__(1024, 1) k_admm(float* __restrict__ out) {
    extern __shared__ float smx[];
    float* X   = smx;              // 4160 each
    float* Rr  = smx + 4160;
    float* Dd  = smx + 8320;
    float* Pm  = smx + 12480;
    float* RAd = smx + 16640;      // 64 each
    float* CAd = RAd + 64;
    float* RBd = CAd + 64;
    float* CBd = RBd + 64;
    float* RAr = CBd + 64;
    float* CAr = RAr + 64;
    float* RSQ = CAr + 64;
    float* RX  = RSQ + 64;
    float* CX  = RX + 64;
    float* y2r = CX + 64;
    float* y2c = y2r + 64;
    float* part = y2c + 64;        // 32

    const float rho   = 100.f;
    const float sigma = 1e-3f;
    const float beta  = 3969.f + rho + sigma;
    const float binv  = 1.f / beta;
    const float b64i  = 1.f / (beta + 64.f * rho);
    const float b128i = 1.f / (beta + 128.f * rho);
    const float cRC   = (b64i - binv) * (1.f / 64.f);
    const float cT    = (b128i - 2.f * b64i + binv) * (1.f / 4096.f);

    const int tid = threadIdx.x;
    const int w = tid >> 5, lane = tid & 31;
    const int g = lane & 15, h = lane >> 4;
    const int a0 = tid >> 6, b0 = tid & 63;
    const int rc = 2 * w + h;      // row/col index this half-warp reduces

    int aa[4], off[4];
#pragma unroll
    for (int k = 0; k < 4; k++) { aa[k] = a0 + 16 * k; off[k] = aa[k] * LD + b0; }

    float x[4], xr[4], z1[4], y1[4], r[4], p[4], dreg[4];
#pragma unroll
    for (int k = 0; k < 4; k++) {
        p[k] = g_P[aa[k] * 64 + b0];
        Pm[off[k]] = p[k];
        X[off[k]] = 0.f;
        x[k] = xr[k] = z1[k] = y1[k] = 0.f;
    }
    if (tid < 64) { y2r[tid] = 0.f; y2c[tid] = 0.f; }
    __syncthreads();

    float TA = 0.f, TB = 0.f, TR = 0.f, N2 = 0.f, SR2 = 0.f, SC2 = 0.f;
    float tol2 = 1e30f;

    // row/col/total sums of M and P.*M  (1 barrier; totals redundant per warp)
    auto sums2 = [&](const float* M) {
        float sv = 0.f, sp = 0.f;
#pragma unroll
        for (int j = 0; j < 4; j++) {
            int o = rc * LD + g + 16 * j;
            float m = M[o], q = Pm[o];
            sv += m; sp += q * m;
        }
        sv = dual16(sv); sp = dual16(sp);
        if (!g) { RAd[rc] = sv; RBd[rc] = sp; }
        float cv = 0.f, cp = 0.f;
#pragma unroll
        for (int j = 0; j < 4; j++) {
            int o = (g + 16 * j) * LD + rc;
            float m = M[o], q = Pm[o];
            cv += m; cp += q * m;
        }
        cv = dual16(cv); cp = dual16(cp);
        if (!g) { CAd[rc] = cv; CBd[rc] = cp; }
        __syncthreads();
        TA = warpSum(RAd[lane] + RAd[lane + 32]);
        TB = warpSum(RBd[lane] + RBd[lane + 32]);
    };

    // row/col sums + rowsq of Rr; totals TR, N2=|r|^2, SR2, SC2 (1 barrier)
    auto phaseR = [&]() {
        float sv = 0.f, sq = 0.f;
#pragma unroll
        for (int j = 0; j < 4; j++) {
            float v = Rr[rc * LD + g + 16 * j];
            sv += v; sq += v * v;
        }
        sv = dual16(sv); sq = dual16(sq);
        if (!g) { RAr[rc] = sv; RSQ[rc] = sq; }
        float cv = 0.f;
#pragma unroll
        for (int j = 0; j < 4; j++) cv += Rr[(g + 16 * j) * LD + rc];
        cv = dual16(cv);
        if (!g) CAr[rc] = cv;
        __syncthreads();
        TR  = warpSum(RAr[lane] + RAr[lane + 32]);
        N2  = warpSum(RSQ[lane] + RSQ[lane + 32]);
        SR2 = warpSum(RAr[lane] * RAr[lane] + RAr[lane + 32] * RAr[lane + 32]);
        SC2 = warpSum(CAr[lane] * CAr[lane] + CAr[lane + 32] * CAr[lane + 32]);
    };

    auto applyK = [&](float d, float pp, int a) -> float {
        float Ra = RAd[a], Cb = CAd[b0], Rb = RBd[a], Cv = CBd[b0];
        return beta * d + rho * (Ra + Cb)
             - 0.5f * (pp * (TA - Ra - Cb + d) + (TB - Rb - Cv + pp * d));
    };

    for (int it = 0; it < 150; ++it) {
        if ((it & 7) == 0) {
            // residual from scratch: r = rhs - K x
            sums2(X);
            float loc = 0.f;
#pragma unroll
            for (int k = 0; k < 4; k++) {
                float kx = applyK(x[k], p[k], aa[k]);
                float rhs = sigma * x[k] + p[k] + (rho * z1[k] - y1[k])
                          + (rho - y2c[b0]) + (rho - y2r[aa[k]]);
                r[k] = rhs - kx;
                Rr[off[k]] = r[k];
                loc += rhs * rhs;
            }
            loc = warpSum(loc);
            if (!lane) part[w] = loc;
            __syncthreads();
            float nr = warpSum(part[lane]);
            tol2 = fmaxf(nr * 1e-12f, 1e-28f);
        }

        phaseR();  // TR,N2,SR2,SC2 for current r

        if (N2 > tol2) {
            float rho_s = binv * N2 + cRC * (SR2 + SC2) + cT * TR * TR;
            // d0 = B^-1 r
#pragma unroll
            for (int k = 0; k < 4; k++) {
                float z = binv * r[k] + cRC * (RAr[aa[k]] + CAr[b0]) + cT * TR;
                dreg[k] = z;
                Dd[off[k]] = z;
            }
            __syncthreads();

            float prev = 3.4e38f;
            int stag = 0;
            for (int cg = 0; cg < 120; ++cg) {
                // A: sums of d
                sums2(Dd);
                // B: q = K d, alpha
                float q[4];
                float loc = 0.f;
#pragma unroll
                for (int k = 0; k < 4; k++) {
                    q[k] = applyK(dreg[k], p[k], aa[k]);
                    loc += dreg[k] * q[k];
                }
                loc = warpSum(loc);
                if (!lane) part[w] = loc;
                __syncthreads();
                float dq = warpSum(part[lane]);
                if (!(dq > 0.f)) break;
                float alpha = rho_s / dq;
                // C: x, r update
#pragma unroll
                for (int k = 0; k < 4; k++) {
                    x[k] += alpha * dreg[k];
                    r[k] -= alpha * q[k];
                    Rr[off[k]] = r[k];
                }
                __syncthreads();
                // D: sums of r  -> precond scalars (closed-form rho)
                phaseR();
                if (N2 <= tol2) break;
                if (N2 >= 0.99f * prev) { if (++stag >= 3) break; }
                else stag = 0;
                prev = N2;
                float rho_n = binv * N2 + cRC * (SR2 + SC2) + cT * TR * TR;
                float bk = rho_n / rho_s;
                rho_s = rho_n;
                // E: d = z + bk*d
#pragma unroll
                for (int k = 0; k < 4; k++) {
                    float z = binv * r[k] + cRC * (RAr[aa[k]] + CAr[b0]) + cT * TR;
                    dreg[k] = z + bk * dreg[k];
                    Dd[off[k]] = dreg[k];
                }
                __syncthreads();
            }
        }

        // publish x, get row/col sums of x
#pragma unroll
        for (int k = 0; k < 4; k++) X[off[k]] = x[k];
        __syncthreads();
        {
            float sv = 0.f;
#pragma unroll
            for (int j = 0; j < 4; j++) sv += X[rc * LD + g + 16 * j];
            sv = dual16(sv);
            if (!g) RX[rc] = sv;
            float cv = 0.f;
#pragma unroll
            for (int j = 0; j < 4; j++) cv += X[(g + 16 * j) * LD + rc];
            cv = dual16(cv);
            if (!g) CX[rc] = cv;
        }
        __syncthreads();
        // z/y updates + incremental residual for next outer
#pragma unroll
        for (int k = 0; k < 4; k++) {
            float z1n = fminf(fmaxf(x[k] + y1[k] * (1.f / rho), 0.f), 1e6f);
            float rinc = sigma * (x[k] - xr[k]) + rho * (2.f * z1n - z1[k] - x[k])
                       - rho * (CX[b0] - 1.f) - rho * (RX[aa[k]] - 1.f);
            y1[k] += rho * (x[k] - z1n);
            z1[k] = z1n;
            r[k] += rinc;
            Rr[off[k]] = r[k];
            xr[k] = x[k];
        }
        if (tid < 64) {
            y2c[tid] += rho * (CX[tid] - 1.f);
            y2r[tid] += rho * (RX[tid] - 1.f);
        }
        __syncthreads();
    }

    // out[0][j][i] = softmax_i( 200 * clip(X[i][j],0,1) ) : column-wise softmax of X
#pragma unroll
    for (int rr = 0; rr < 2; rr++) {
        int c = 2 * w + rr;
        float v1 = fminf(fmaxf(X[lane * LD + c], 0.f), 1.f);
        float v2 = fminf(fmaxf(X[(lane + 32) * LD + c], 0.f), 1.f);
        float mx = warpMax(fmaxf(v1, v2));
        float e1v = expf(200.f * (v1 - mx));
        float e2v = expf(200.f * (v2 - mx));
        float s = warpSum(e1v + e2v);
        out[c * 64 + lane] = e1v / s;
        out[c * 64 + lane + 32] = e2v / s;
    }
}

// ------------------------------------------------------------------------------------
extern "C" void kernel_launch(void* const* d_in, const int* in_sizes, int n_in,
                              void* d_out, int out_size) {
    const float* tra = (const float*)d_in[0];   // (64,512)
    const float* det = (const float*)d_in[1];   // (64,512)
    const float* iou = (const float*)d_in[2];   // (64,64)
    const float* W   = (const float*)d_in[3];   // (512,512)
    const float* b   = (const float*)d_in[4];   // (512,)
    float* out = (float*)d_out;                 // (1,64,64)

    const int SMEM_BYTES = (16640 + 11 * 64 + 32) * 4;  // 69504
    cudaFuncSetAttribute(k_admm, cudaFuncAttributeMaxDynamicSharedMemorySize, SMEM_BYTES);

    k_mp0<<<128, 1024>>>(tra, det, iou);
    k_m12<<<64, 1024>>>(tra, det);
    k_u<<<128, 512>>>(tra, det);
    k_egemm<<<2048, 1024>>>(W, b);
    k_enorm<<<128, 512>>>();
    k_P<<<128, 1024>>>();
    k_admm<<<1, 1024, SMEM_BYTES>>>(out);
}

// round 6
// speedup vs baseline: 1.9670x; 1.5193x over previous
#include <cuda_runtime.h>
#include <math.h>

#define LD 65  // padded row stride for 64x64 tiles in smem

// ---------------- intermediates (device globals; no allocation allowed) -----------
__device__ float g_Mp0[64 * 64];
__device__ float g_m1[64 * 512];
__device__ float g_m2[64 * 512];
__device__ float g_u1[64 * 512];
__device__ float g_u2[64 * 512];
__device__ float g_e1[64 * 512];
__device__ float g_e2[64 * 512];
__device__ float g_P[64 * 64];   // P[a,b] = e1[b] . e2[a]

__device__ __forceinline__ float warpSum(float v) {
#pragma unroll
    for (int o = 16; o; o >>= 1) v += __shfl_xor_sync(0xffffffffu, v, o);
    return v;
}
__device__ __forceinline__ float warpMax(float v) {
#pragma unroll
    for (int o = 16; o; o >>= 1) v = fmaxf(v, __shfl_xor_sync(0xffffffffu, v, o));
    return v;
}
// reduce within each 16-lane half of a warp (4 steps)
__device__ __forceinline__ float dual16(float v) {
#pragma unroll
    for (int o = 8; o; o >>= 1) v += __shfl_xor_sync(0xffffffffu, v, o);
    return v;
}

// ---------------- Mp0 = feat_tra @ feat_det^T + iou : warp per output -------------
__global__ void k_mp0(const float* __restrict__ tra, const float* __restrict__ det,
                      const float* __restrict__ iou) {
    int gw = blockIdx.x * 32 + (threadIdx.x >> 5);
    int lane = threadIdx.x & 31;
    int i = gw >> 6, j = gw & 63;
    const float* a = tra + i * 512;
    const float* b = det + j * 512;
    float s = 0.f;
#pragma unroll 4
    for (int k = lane; k < 512; k += 32) s += a[k] * b[k];
    s = warpSum(s);
    if (!lane) g_Mp0[i * 64 + j] = s + iou[i * 64 + j];
}

// ---------------- m1 = Mp0 @ det, m2 = Mp0^T @ tra --------------------------------
__global__ void k_m12(const float* __restrict__ tra, const float* __restrict__ det) {
    int t = blockIdx.x * blockDim.x + threadIdx.x;
    if (t < 32768) {
        int i = t >> 9, k = t & 511;
        float s = 0.f;
#pragma unroll 8
        for (int j = 0; j < 64; j++) s += g_Mp0[i * 64 + j] * det[j * 512 + k];
        g_m1[t] = s;
    } else {
        int t2 = t - 32768;
        int j = t2 >> 9, k = t2 & 511;
        float s = 0.f;
#pragma unroll 8
        for (int i = 0; i < 64; i++) s += g_Mp0[i * 64 + j] * tra[i * 512 + k];
        g_m2[t2] = s;
    }
}

// ---------------- u = feat + lam * m ----------------------------------------------
__global__ void k_u(const float* __restrict__ tra, const float* __restrict__ det) {
    __shared__ float pf[16], pm[16];
    __shared__ float sLam;
    int rr = blockIdx.x;
    const float* f;
    const float* m;
    float* u;
    if (rr < 64) { f = tra + rr * 512; m = g_m1 + rr * 512; u = g_u1 + rr * 512; }
    else         { rr -= 64; f = det + rr * 512; m = g_m2 + rr * 512; u = g_u2 + rr * 512; }
    int t = threadIdx.x;
    float fv = f[t], mv = m[t];
    float sf = warpSum(fv * fv);
    float smv = warpSum(mv * mv);
    int w = t >> 5, lane = t & 31;
    if (!lane) { pf[w] = sf; pm[w] = smv; }
    __syncthreads();
    if (t < 32) {
        float a = (t < 16) ? pf[t] : 0.f;
        float b = (t < 16) ? pm[t] : 0.f;
        a = warpSum(a);
        b = warpSum(b);
        if (!t) sLam = sqrtf(a) / sqrtf(b);
    }
    __syncthreads();
    u[t] = fv + sLam * mv;
}

// ---------------- e = relu(u @ W^T + b) : warp per output -------------------------
__global__ void k_egemm(const float* __restrict__ W, const float* __restrict__ bias) {
    int gw = blockIdx.x * 32 + (threadIdx.x >> 5);
    int lane = threadIdx.x & 31;
    int tensor = gw >> 15;
    int loc = gw & 32767;
    int i = loc >> 9, j = loc & 511;
    const float* u = (tensor ? g_u2 : g_u1) + i * 512;
    const float* wv = W + j * 512;
    float s = 0.f;
#pragma unroll 4
    for (int k = lane; k < 512; k += 32) s += u[k] * wv[k];
    s = warpSum(s);
    if (!lane) {
        float v = fmaxf(s + bias[j], 0.f);
        (tensor ? g_e2 : g_e1)[i * 512 + j] = v;
    }
}

// ---------------- row-wise L2 normalize e in place --------------------------------
__global__ void k_enorm() {
    __shared__ float pp[16];
    __shared__ float sScale;
    int rr = blockIdx.x;
    float* e = (rr < 64) ? (g_e1 + rr * 512) : (g_e2 + (rr - 64) * 512);
    int t = threadIdx.x;
    float v = e[t];
    float s = warpSum(v * v);
    if (!(t & 31)) pp[t >> 5] = s;
    __syncthreads();
    if (t < 32) {
        float a = (t < 16) ? pp[t] : 0.f;
        a = warpSum(a);
        if (!t) sScale = 1.f / fmaxf(sqrtf(a), 1e-12f);
    }
    __syncthreads();
    e[t] = v * sScale;
}

// ---------------- P[a,b] = e1[b] . e2[a] ------------------------------------------
__global__ void k_P() {
    int gw = blockIdx.x * 32 + (threadIdx.x >> 5);
    int lane = threadIdx.x & 31;
    int a = gw >> 6, b = gw & 63;
    const float* x = g_e1 + b * 512;
    const float* y = g_e2 + a * 512;
    float s = 0.f;
#pragma unroll 4
    for (int k = lane; k < 512; k += 32) s += x[k] * y[k];
    s = warpSum(s);
    if (!lane) g_P[a * 64 + b] = s;
}

// ---------------- ADMM + PCG with rank-2 Woodbury preconditioner -------------------
// K = beta*I + rho*(I(x)J + J(x)I) - 0.5*(D_p*S + S*D_p),  S = (J-I)(x)(J-I)
// S = E E^T - (J(x)I) - (I(x)J) + I  (E = ones(4096)), so
// K = B2 - 0.5*(D_p*St + St*D_p),  St d = d - Rd_a - Cd_b  (norm <= 63 on 126-dim subspace)
// B2 = B - 0.5*(p E^T + E p^T),  B = beta*I + rho*(I(x)J + J(x)I)
// Woodbury: B2^-1 r = B^-1 r + [w_p w_E] Hinv [p.(B^-1 r); sum(B^-1 r)],
//   w_p = B^-1 p (precomputed),  w_E = b128i * ones,
//   H = Ginv - M^T B^-1 M = [[-pBp, 2 - b128i*TP], [2 - b128i*TP, -4096*b128i]]
// All dots needed are closed-form from row/col sums (phaseR strips).
__global__ void __launch_bounds__(1024, 1) k_admm(float* __restrict__ out) {
    extern __shared__ float smx[];
    float* X   = smx;              // 4160 each
    float* Rr  = smx + 4160;
    float* Dd  = smx + 8320;
    float* Pm  = smx + 12480;
    float* RAd = smx + 16640;      // 64 each
    float* CAd = RAd + 64;
    float* RBd = CAd + 64;
    float* CBd = RBd + 64;
    float* RAr = CBd + 64;
    float* CAr = RAr + 64;
    float* RSQ = CAr + 64;
    float* RPR = RSQ + 64;
    float* RP  = RPR + 64;
    float* CP  = RP + 64;
    float* RX  = CP + 64;
    float* CX  = RX + 64;
    float* y2r = CX + 64;
    float* y2c = y2r + 64;
    float* part = y2c + 64;        // 32
    float* scal = part + 32;       // 8

    const float rho   = 100.f;
    const float sigma = 1e-3f;
    const float beta  = 3969.f + rho + sigma;
    const float binv  = 1.f / beta;
    const float b64i  = 1.f / (beta + 64.f * rho);
    const float b128i = 1.f / (beta + 128.f * rho);
    const float cRC   = (b64i - binv) * (1.f / 64.f);
    const float cT    = (b128i - 2.f * b64i + binv) * (1.f / 4096.f);

    const int tid = threadIdx.x;
    const int w = tid >> 5, lane = tid & 31;
    const int g = lane & 15, h = lane >> 4;
    const int a0 = tid >> 6, b0 = tid & 63;
    const int rc = 2 * w + h;      // row/col index this half-warp reduces

    int aa[4], off[4];
#pragma unroll
    for (int k = 0; k < 4; k++) { aa[k] = a0 + 16 * k; off[k] = aa[k] * LD + b0; }

    float x[4], xr[4], z1[4], y1[4], r[4], p[4], dreg[4], wp[4];
#pragma unroll
    for (int k = 0; k < 4; k++) {
        p[k] = g_P[aa[k] * 64 + b0];
        Pm[off[k]] = p[k];
        X[off[k]] = 0.f;
        x[k] = xr[k] = z1[k] = y1[k] = 0.f;
    }
    if (tid < 64) { y2r[tid] = 0.f; y2c[tid] = 0.f; }
    __syncthreads();

    // ---- init: sums over P for the Woodbury preconditioner ----
    {
        float sv = 0.f, sq = 0.f;
#pragma unroll
        for (int j = 0; j < 4; j++) {
            float v = Pm[rc * LD + g + 16 * j];
            sv += v; sq += v * v;
        }
        sv = dual16(sv); sq = dual16(sq);
        if (!g) { RP[rc] = sv; RSQ[rc] = sq; }
        float cv = 0.f;
#pragma unroll
        for (int j = 0; j < 4; j++) cv += Pm[(g + 16 * j) * LD + rc];
        cv = dual16(cv);
        if (!g) CP[rc] = cv;
        __syncthreads();
        if (w == 0)      { float v = warpSum(RP[lane] + RP[lane + 32]);  if (!lane) scal[5] = v; }
        else if (w == 1) { float v = warpSum(RSQ[lane] + RSQ[lane + 32]); if (!lane) scal[6] = v; }
        else if (w == 2) { float v = warpSum(RP[lane] * RP[lane] + RP[lane + 32] * RP[lane + 32]
                                           + CP[lane] * CP[lane] + CP[lane + 32] * CP[lane + 32]);
                           if (!lane) scal[7] = v; }
        __syncthreads();
    }
    const float TP = scal[5];
    const float P2 = scal[6];
    const float SRCP2 = scal[7];
    const float pBp = binv * P2 + cRC * SRCP2 + cT * TP * TP;
    const float h12v = 2.f - b128i * TP;
    const float h11v = -pBp;
    const float h22v = -4096.f * b128i;
    const float hdet = h11v * h22v - h12v * h12v;
    const float i11 = h22v / hdet, i12 = -h12v / hdet, i22 = h11v / hdet;
#pragma unroll
    for (int k = 0; k < 4; k++)
        wp[k] = binv * p[k] + cRC * (RP[aa[k]] + CP[b0]) + cT * TP;

    float TA = 0.f, TB = 0.f;
    float TR = 0.f, N2 = 0.f, SRC2 = 0.f, SPC = 0.f, PR = 0.f;
    float tol2 = 1e30f;

    // row/col/total sums of M and P.*M  (1 barrier; 2 totals redundant per warp)
    auto sums2 = [&](const float* M) {
        float sv = 0.f, sp = 0.f;
#pragma unroll
        for (int j = 0; j < 4; j++) {
            int o = rc * LD + g + 16 * j;
            float m = M[o], q = Pm[o];
            sv += m; sp += q * m;
        }
        sv = dual16(sv); sp = dual16(sp);
        if (!g) { RAd[rc] = sv; RBd[rc] = sp; }
        float cv = 0.f, cp = 0.f;
#pragma unroll
        for (int j = 0; j < 4; j++) {
            int o = (g + 16 * j) * LD + rc;
            float m = M[o], q = Pm[o];
            cv += m; cp += q * m;
        }
        cv = dual16(cv); cp = dual16(cp);
        if (!g) { CAd[rc] = cv; CBd[rc] = cp; }
        __syncthreads();
        TA = warpSum(RAd[lane] + RAd[lane + 32]);
        TB = warpSum(RBd[lane] + RBd[lane + 32]);
    };

    // sums over r: row sums, col sums, |r|^2, p.r, and finalize 5 scalars (2 barriers)
    auto phaseR = [&]() {
        float sv = 0.f, sq = 0.f, pv = 0.f;
#pragma unroll
        for (int j = 0; j < 4; j++) {
            int o = rc * LD + g + 16 * j;
            float v = Rr[o];
            sv += v; sq += v * v; pv += Pm[o] * v;
        }
        sv = dual16(sv); sq = dual16(sq); pv = dual16(pv);
        if (!g) { RAr[rc] = sv; RSQ[rc] = sq; RPR[rc] = pv; }
        float cv = 0.f;
#pragma unroll
        for (int j = 0; j < 4; j++) cv += Rr[(g + 16 * j) * LD + rc];
        cv = dual16(cv);
        if (!g) CAr[rc] = cv;
        __syncthreads();
        if (w == 0)      { float v = warpSum(RAr[lane] + RAr[lane + 32]); if (!lane) scal[0] = v; }
        else if (w == 1) { float v = warpSum(RSQ[lane] + RSQ[lane + 32]); if (!lane) scal[1] = v; }
        else if (w == 2) { float v = warpSum(RAr[lane] * RAr[lane] + RAr[lane + 32] * RAr[lane + 32]
                                           + CAr[lane] * CAr[lane] + CAr[lane + 32] * CAr[lane + 32]);
                           if (!lane) scal[2] = v; }
        else if (w == 3) { float v = warpSum(RP[lane] * RAr[lane] + RP[lane + 32] * RAr[lane + 32]
                                           + CP[lane] * CAr[lane] + CP[lane + 32] * CAr[lane + 32]);
                           if (!lane) scal[3] = v; }
        else if (w == 4) { float v = warpSum(RPR[lane] + RPR[lane + 32]); if (!lane) scal[4] = v; }
        __syncthreads();
        TR = scal[0]; N2 = scal[1]; SRC2 = scal[2]; SPC = scal[3]; PR = scal[4];
    };

    auto applyK = [&](float d, float pp, int a) -> float {
        float Ra = RAd[a], Cb = CAd[b0], Rb = RBd[a], Cv = CBd[b0];
        return beta * d + rho * (Ra + Cb)
             - 0.5f * (pp * (TA - Ra - Cb + d) + (TB - Rb - Cv + pp * d));
    };

    // Woodbury scalars from current phaseR results
    float s1 = 0.f, s2 = 0.f, al1 = 0.f, al2 = 0.f, rhoz = 0.f;
    auto wood = [&]() {
        s1 = binv * PR + cRC * SPC + cT * TP * TR;
        s2 = b128i * TR;
        al1 = i11 * s1 + i12 * s2;
        al2 = i12 * s1 + i22 * s2;
        rhoz = binv * N2 + cRC * SRC2 + cT * TR * TR + al1 * s1 + al2 * s2;
    };

    for (int it = 0; it < 150; ++it) {
        if ((it & 7) == 0) {
            // residual from scratch: r = rhs - K x
            sums2(X);
            float loc = 0.f;
#pragma unroll
            for (int k = 0; k < 4; k++) {
                float kx = applyK(x[k], p[k], aa[k]);
                float rhs = sigma * x[k] + p[k] + (rho * z1[k] - y1[k])
                          + (rho - y2c[b0]) + (rho - y2r[aa[k]]);
                r[k] = rhs - kx;
                Rr[off[k]] = r[k];
                loc += rhs * rhs;
            }
            loc = warpSum(loc);
            if (!lane) part[w] = loc;
            __syncthreads();
            float nr = warpSum(part[lane]);
            tol2 = fmaxf(nr * 1e-10f, 1e-28f);
        }

        phaseR();

        if (N2 > tol2) {
            wood();
            float rho_s = rhoz;
            // d0 = B2^-1 r
#pragma unroll
            for (int k = 0; k < 4; k++) {
                float z = binv * r[k] + cRC * (RAr[aa[k]] + CAr[b0]) + cT * TR
                        + al1 * wp[k] + al2 * b128i;
                dreg[k] = z;
                Dd[off[k]] = z;
            }
            __syncthreads();

            float prev = 3.4e38f;
            int stag = 0;
            for (int cg = 0; cg < 60; ++cg) {
                // A: sums of d
                sums2(Dd);
                // B: q = K d, alpha
                float q[4];
                float loc = 0.f;
#pragma unroll
                for (int k = 0; k < 4; k++) {
                    q[k] = applyK(dreg[k], p[k], aa[k]);
                    loc += dreg[k] * q[k];
                }
                loc = warpSum(loc);
                if (!lane) part[w] = loc;
                __syncthreads();
                float dq = warpSum(part[lane]);
                if (!(dq > 0.f)) break;
                float alpha = rho_s / dq;
                // C: x, r update
#pragma unroll
                for (int k = 0; k < 4; k++) {
                    x[k] += alpha * dreg[k];
                    r[k] -= alpha * q[k];
                    Rr[off[k]] = r[k];
                }
                __syncthreads();
                // D: sums of r -> closed-form precond scalars
                phaseR();
                if (N2 <= tol2) break;
                if (N2 >= 0.99f * prev) { if (++stag >= 3) break; }
                else stag = 0;
                prev = N2;
                wood();
                float bk = rhoz / rho_s;
                rho_s = rhoz;
                // E: d = z + bk*d
#pragma unroll
                for (int k = 0; k < 4; k++) {
                    float z = binv * r[k] + cRC * (RAr[aa[k]] + CAr[b0]) + cT * TR
                            + al1 * wp[k] + al2 * b128i;
                    dreg[k] = z + bk * dreg[k];
                    Dd[off[k]] = dreg[k];
                }
                __syncthreads();
            }
        }

        // publish x, get row/col sums of x
#pragma unroll
        for (int k = 0; k < 4; k++) X[off[k]] = x[k];
        __syncthreads();
        {
            float sv = 0.f;
#pragma unroll
            for (int j = 0; j < 4; j++) sv += X[rc * LD + g + 16 * j];
            sv = dual16(sv);
            if (!g) RX[rc] = sv;
            float cv = 0.f;
#pragma unroll
            for (int j = 0; j < 4; j++) cv += X[(g + 16 * j) * LD + rc];
            cv = dual16(cv);
            if (!g) CX[rc] = cv;
        }
        __syncthreads();
        // z/y updates + incremental residual for next outer
#pragma unroll
        for (int k = 0; k < 4; k++) {
            float z1n = fminf(fmaxf(x[k] + y1[k] * (1.f / rho), 0.f), 1e6f);
            float rinc = sigma * (x[k] - xr[k]) + rho * (2.f * z1n - z1[k] - x[k])
                       - rho * (CX[b0] - 1.f) - rho * (RX[aa[k]] - 1.f);
            y1[k] += rho * (x[k] - z1n);
            z1[k] = z1n;
            r[k] += rinc;
            Rr[off[k]] = r[k];
            xr[k] = x[k];
        }
        if (tid < 64) {
            y2c[tid] += rho * (CX[tid] - 1.f);
            y2r[tid] += rho * (RX[tid] - 1.f);
        }
        __syncthreads();
    }

    // out[0][j][i] = softmax_i( 200 * clip(X[i][j],0,1) ) : column-wise softmax of X
#pragma unroll
    for (int rr = 0; rr < 2; rr++) {
        int c = 2 * w + rr;
        float v1 = fminf(fmaxf(X[lane * LD + c], 0.f), 1.f);
        float v2 = fminf(fmaxf(X[(lane + 32) * LD + c], 0.f), 1.f);
        float mx = warpMax(fmaxf(v1, v2));
        float e1v = expf(200.f * (v1 - mx));
        float e2v = expf(200.f * (v2 - mx));
        float s = warpSum(e1v + e2v);
        out[c * 64 + lane] = e1v / s;
        out[c * 64 + lane + 32] = e2v / s;
    }
}

// ------------------------------------------------------------------------------------
extern "C" void kernel_launch(void* const* d_in, const int* in_sizes, int n_in,
                              void* d_out, int out_size) {
    const float* tra = (const float*)d_in[0];   // (64,512)
    const float* det = (const float*)d_in[1];   // (64,512)
    const float* iou = (const float*)d_in[2];   // (64,64)
    const float* W   = (const float*)d_in[3];   // (512,512)
    const float* b   = (const float*)d_in[4];   // (512,)
    float* out = (float*)d_out;                 // (1,64,64)

    const int SMEM_BYTES = (16640 + 14 * 64 + 32 + 8) * 4;  // 70304
    cudaFuncSetAttribute(k_admm, cudaFuncAttributeMaxDynamicSharedMemorySize, SMEM_BYTES);

    k_mp0<<<128, 1024>>>(tra, det, iou);
    k_m12<<<64, 1024>>>(tra, det);
    k_u<<<128, 512>>>(tra, det);
    k_egemm<<<2048, 1024>>>(W, b);
    k_enorm<<<128, 512>>>();
    k_P<<<128, 1024>>>();
    k_admm<<<1, 1024, SMEM_BYTES>>>(out);
}

// round 7
// speedup vs baseline: 7.3477x; 3.7355x over previous
#include <cuda_runtime.h>
#include <math.h>

#define LD 65  // padded row stride for 64x64 tiles in smem

// ---------------- intermediates (device globals; no allocation allowed) -----------
__device__ float g_Mp0[64 * 64];
__device__ float g_m1[64 * 512];
__device__ float g_m2[64 * 512];
__device__ float g_u1[64 * 512];
__device__ float g_u2[64 * 512];
__device__ float g_e1[64 * 512];
__device__ float g_e2[64 * 512];
__device__ float g_P[64 * 64];   // P[a,b] = e1[b] . e2[a]

__device__ __forceinline__ float warpSum(float v) {
#pragma unroll
    for (int o = 16; o; o >>= 1) v += __shfl_xor_sync(0xffffffffu, v, o);
    return v;
}
__device__ __forceinline__ float warpMax(float v) {
#pragma unroll
    for (int o = 16; o; o >>= 1) v = fmaxf(v, __shfl_xor_sync(0xffffffffu, v, o));
    return v;
}
// reduce within each 16-lane half of a warp (4 steps)
__device__ __forceinline__ float dual16(float v) {
#pragma unroll
    for (int o = 8; o; o >>= 1) v += __shfl_xor_sync(0xffffffffu, v, o);
    return v;
}

// ---------------- Mp0 = feat_tra @ feat_det^T + iou : warp per output -------------
__global__ void k_mp0(const float* __restrict__ tra, const float* __restrict__ det,
                      const float* __restrict__ iou) {
    int gw = blockIdx.x * 32 + (threadIdx.x >> 5);
    int lane = threadIdx.x & 31;
    int i = gw >> 6, j = gw & 63;
    const float* a = tra + i * 512;
    const float* b = det + j * 512;
    float s = 0.f;
#pragma unroll 4
    for (int k = lane; k < 512; k += 32) s += a[k] * b[k];
    s = warpSum(s);
    if (!lane) g_Mp0[i * 64 + j] = s + iou[i * 64 + j];
}

// ---------------- m1 = Mp0 @ det, m2 = Mp0^T @ tra --------------------------------
__global__ void k_m12(const float* __restrict__ tra, const float* __restrict__ det) {
    int t = blockIdx.x * blockDim.x + threadIdx.x;
    if (t < 32768) {
        int i = t >> 9, k = t & 511;
        float s = 0.f;
#pragma unroll 8
        for (int j = 0; j < 64; j++) s += g_Mp0[i * 64 + j] * det[j * 512 + k];
        g_m1[t] = s;
    } else {
        int t2 = t - 32768;
        int j = t2 >> 9, k = t2 & 511;
        float s = 0.f;
#pragma unroll 8
        for (int i = 0; i < 64; i++) s += g_Mp0[i * 64 + j] * tra[i * 512 + k];
        g_m2[t2] = s;
    }
}

// ---------------- u = feat + lam * m ----------------------------------------------
__global__ void k_u(const float* __restrict__ tra, const float* __restrict__ det) {
    __shared__ float pf[16], pm[16];
    __shared__ float sLam;
    int rr = blockIdx.x;
    const float* f;
    const float* m;
    float* u;
    if (rr < 64) { f = tra + rr * 512; m = g_m1 + rr * 512; u = g_u1 + rr * 512; }
    else         { rr -= 64; f = det + rr * 512; m = g_m2 + rr * 512; u = g_u2 + rr * 512; }
    int t = threadIdx.x;
    float fv = f[t], mv = m[t];
    float sf = warpSum(fv * fv);
    float smv = warpSum(mv * mv);
    int w = t >> 5, lane = t & 31;
    if (!lane) { pf[w] = sf; pm[w] = smv; }
    __syncthreads();
    if (t < 32) {
        float a = (t < 16) ? pf[t] : 0.f;
        float b = (t < 16) ? pm[t] : 0.f;
        a = warpSum(a);
        b = warpSum(b);
        if (!t) sLam = sqrtf(a) / sqrtf(b);
    }
    __syncthreads();
    u[t] = fv + sLam * mv;
}

// ---------------- e = relu(u @ W^T + b) : warp per output -------------------------
__global__ void k_egemm(const float* __restrict__ W, const float* __restrict__ bias) {
    int gw = blockIdx.x * 32 + (threadIdx.x >> 5);
    int lane = threadIdx.x & 31;
    int tensor = gw >> 15;
    int loc = gw & 32767;
    int i = loc >> 9, j = loc & 511;
    const float* u = (tensor ? g_u2 : g_u1) + i * 512;
    const float* wv = W + j * 512;
    float s = 0.f;
#pragma unroll 4
    for (int k = lane; k < 512; k += 32) s += u[k] * wv[k];
    s = warpSum(s);
    if (!lane) {
        float v = fmaxf(s + bias[j], 0.f);
        (tensor ? g_e2 : g_e1)[i * 512 + j] = v;
    }
}

// ---------------- row-wise L2 normalize e in place --------------------------------
__global__ void k_enorm() {
    __shared__ float pp[16];
    __shared__ float sScale;
    int rr = blockIdx.x;
    float* e = (rr < 64) ? (g_e1 + rr * 512) : (g_e2 + (rr - 64) * 512);
    int t = threadIdx.x;
    float v = e[t];
    float s = warpSum(v * v);
    if (!(t & 31)) pp[t >> 5] = s;
    __syncthreads();
    if (t < 32) {
        float a = (t < 16) ? pp[t] : 0.f;
        a = warpSum(a);
        if (!t) sScale = 1.f / fmaxf(sqrtf(a), 1e-12f);
    }
    __syncthreads();
    e[t] = v * sScale;
}

// ---------------- P[a,b] = e1[b] . e2[a] ------------------------------------------
__global__ void k_P() {
    int gw = blockIdx.x * 32 + (threadIdx.x >> 5);
    int lane = threadIdx.x & 31;
    int a = gw >> 6, b = gw & 63;
    const float* x = g_e1 + b * 512;
    const float* y = g_e2 + a * 512;
    float s = 0.f;
#pragma unroll 4
    for (int k = lane; k < 512; k += 32) s += x[k] * y[k];
    s = warpSum(s);
    if (!lane) g_P[a * 64 + b] = s;
}

// ---------------- ADMM + PCG, Woodbury precond + closed-form alpha -----------------
// K = B2 - 0.5*(D_p*St + St*D_p),  St d = d - Rd_a - Cd_b
// B2 = B - 0.5*(p E^T + E p^T),  B = beta*I + rho*(I(x)J + J(x)I)
// d.Kd = beta*|d|^2 + rho*(sum Rd^2 + sum Cd^2)
//        - ( Td*Te - sum(Rd.RBd) - sum(Cd.CBd) + sum(p d^2) )     [closed form]
__global__ void __launch_bounds__(1024, 1) k_admm(float* __restrict__ out) {
    extern __shared__ float smx[];
    float* X    = smx;             // 4160 each
    float* Rr   = smx + 4160;
    float* Dd   = smx + 8320;
    float* Pm   = smx + 12480;
    float* RAd  = smx + 16640;     // 64 each
    float* CAd  = RAd + 64;
    float* RBd  = CAd + 64;
    float* CBd  = RBd + 64;
    float* RD2  = CBd + 64;
    float* RPD2 = RD2 + 64;
    float* RAr  = RPD2 + 64;
    float* CAr  = RAr + 64;
    float* RSQ  = CAr + 64;
    float* RPR  = RSQ + 64;
    float* RP   = RPR + 64;
    float* CP   = RP + 64;
    float* RX   = CP + 64;
    float* CX   = RX + 64;
    float* y2r  = CX + 64;
    float* y2c  = y2r + 64;
    float* part = y2c + 64;        // 32
    float* scal = part + 32;       // 8

    const float rho   = 100.f;
    const float sigma = 1e-3f;
    const float beta  = 3969.f + rho + sigma;
    const float binv  = 1.f / beta;
    const float b64i  = 1.f / (beta + 64.f * rho);
    const float b128i = 1.f / (beta + 128.f * rho);
    const float cRC   = (b64i - binv) * (1.f / 64.f);
    const float cT    = (b128i - 2.f * b64i + binv) * (1.f / 4096.f);

    const int tid = threadIdx.x;
    const int w = tid >> 5, lane = tid & 31;
    const int g = lane & 15, h = lane >> 4;
    const int a0 = tid >> 6, b0 = tid & 63;
    const int rc = 2 * w + h;      // row/col index this half-warp reduces

    int aa[4], off[4];
#pragma unroll
    for (int k = 0; k < 4; k++) { aa[k] = a0 + 16 * k; off[k] = aa[k] * LD + b0; }

    float x[4], xr[4], z1[4], y1[4], r[4], p[4], dreg[4], wp[4];
#pragma unroll
    for (int k = 0; k < 4; k++) {
        p[k] = g_P[aa[k] * 64 + b0];
        Pm[off[k]] = p[k];
        X[off[k]] = 0.f;
        x[k] = xr[k] = z1[k] = y1[k] = 0.f;
    }
    if (tid < 64) { y2r[tid] = 0.f; y2c[tid] = 0.f; RX[tid] = 0.f; CX[tid] = 0.f; }
    __syncthreads();

    // ---- init: sums over P for Woodbury ----
    {
        float sv = 0.f, sq = 0.f;
#pragma unroll
        for (int j = 0; j < 4; j++) {
            float v = Pm[rc * LD + g + 16 * j];
            sv += v; sq += v * v;
        }
        sv = dual16(sv); sq = dual16(sq);
        if (!g) { RP[rc] = sv; RSQ[rc] = sq; }
        float cv = 0.f;
#pragma unroll
        for (int j = 0; j < 4; j++) cv += Pm[(g + 16 * j) * LD + rc];
        cv = dual16(cv);
        if (!g) CP[rc] = cv;
        __syncthreads();
        if (w == 0)      { float v = warpSum(RP[lane] + RP[lane + 32]);  if (!lane) scal[5] = v; }
        else if (w == 1) { float v = warpSum(RSQ[lane] + RSQ[lane + 32]); if (!lane) scal[6] = v; }
        else if (w == 2) { float v = warpSum(RP[lane] * RP[lane] + RP[lane + 32] * RP[lane + 32]
                                           + CP[lane] * CP[lane] + CP[lane + 32] * CP[lane + 32]);
                           if (!lane) scal[7] = v; }
        __syncthreads();
    }
    const float TP = scal[5];
    const float P2 = scal[6];
    const float SRCP2 = scal[7];
    const float pBp = binv * P2 + cRC * SRCP2 + cT * TP * TP;
    const float h12v = 2.f - b128i * TP;
    const float h11v = -pBp;
    const float h22v = -4096.f * b128i;
    const float hdet = h11v * h22v - h12v * h12v;
    const float i11 = h22v / hdet, i12 = -h12v / hdet, i22 = h11v / hdet;
#pragma unroll
    for (int k = 0; k < 4; k++)
        wp[k] = binv * p[k] + cRC * (RP[aa[k]] + CP[b0]) + cT * TP;

    float TA = 0.f, TB = 0.f, D2 = 0.f, PD2 = 0.f, SA2 = 0.f, SAB = 0.f;
    float TR = 0.f, N2 = 0.f, SRC2 = 0.f, SPC = 0.f, PR = 0.f;
    float tol2 = 1e30f;
    int conv = 0;

    // strips + finalize over d (Dd): RAd,CAd,RBd,CBd + TA,TB,D2,PD2,SA2,SAB (2 barriers)
    auto phaseD = [&]() {
        float sv = 0.f, sp = 0.f, sq = 0.f, spq = 0.f;
#pragma unroll
        for (int j = 0; j < 4; j++) {
            int o = rc * LD + g + 16 * j;
            float m = Dd[o], q = Pm[o];
            sv += m; sp += q * m; sq += m * m; spq += q * m * m;
        }
        sv = dual16(sv); sp = dual16(sp); sq = dual16(sq); spq = dual16(spq);
        if (!g) { RAd[rc] = sv; RBd[rc] = sp; RD2[rc] = sq; RPD2[rc] = spq; }
        float cv = 0.f, cp = 0.f;
#pragma unroll
        for (int j = 0; j < 4; j++) {
            int o = (g + 16 * j) * LD + rc;
            float m = Dd[o];
            cv += m; cp += Pm[o] * m;
        }
        cv = dual16(cv); cp = dual16(cp);
        if (!g) { CAd[rc] = cv; CBd[rc] = cp; }
        __syncthreads();
        if (w == 0)      { float v = warpSum(RAd[lane] + RAd[lane + 32]);  if (!lane) scal[0] = v; }
        else if (w == 1) { float v = warpSum(RBd[lane] + RBd[lane + 32]);  if (!lane) scal[1] = v; }
        else if (w == 2) { float v = warpSum(RD2[lane] + RD2[lane + 32]);  if (!lane) scal[2] = v; }
        else if (w == 3) { float v = warpSum(RPD2[lane] + RPD2[lane + 32]); if (!lane) scal[3] = v; }
        else if (w == 4) { float v = warpSum(RAd[lane] * RAd[lane] + RAd[lane + 32] * RAd[lane + 32]
                                           + CAd[lane] * CAd[lane] + CAd[lane + 32] * CAd[lane + 32]);
                           if (!lane) scal[4] = v; }
        else if (w == 5) { float v = warpSum(RAd[lane] * RBd[lane] + RAd[lane + 32] * RBd[lane + 32]
                                           + CAd[lane] * CBd[lane] + CAd[lane + 32] * CBd[lane + 32]);
                           if (!lane) scal[5] = v; }
        __syncthreads();
        TA = scal[0]; TB = scal[1]; D2 = scal[2]; PD2 = scal[3]; SA2 = scal[4]; SAB = scal[5];
    };

    // sums over r (2 barriers): TR, N2, SRC2, SPC, PR
    auto phaseR = [&]() {
        float sv = 0.f, sq = 0.f, pv = 0.f;
#pragma unroll
        for (int j = 0; j < 4; j++) {
            int o = rc * LD + g + 16 * j;
            float v = Rr[o];
            sv += v; sq += v * v; pv += Pm[o] * v;
        }
        sv = dual16(sv); sq = dual16(sq); pv = dual16(pv);
        if (!g) { RAr[rc] = sv; RSQ[rc] = sq; RPR[rc] = pv; }
        float cv = 0.f;
#pragma unroll
        for (int j = 0; j < 4; j++) cv += Rr[(g + 16 * j) * LD + rc];
        cv = dual16(cv);
        if (!g) CAr[rc] = cv;
        __syncthreads();
        if (w == 0)      { float v = warpSum(RAr[lane] + RAr[lane + 32]); if (!lane) scal[0] = v; }
        else if (w == 1) { float v = warpSum(RSQ[lane] + RSQ[lane + 32]); if (!lane) scal[1] = v; }
        else if (w == 2) { float v = warpSum(RAr[lane] * RAr[lane] + RAr[lane + 32] * RAr[lane + 32]
                                           + CAr[lane] * CAr[lane] + CAr[lane + 32] * CAr[lane + 32]);
                           if (!lane) scal[2] = v; }
        else if (w == 3) { float v = warpSum(RP[lane] * RAr[lane] + RP[lane + 32] * RAr[lane + 32]
                                           + CP[lane] * CAr[lane] + CP[lane + 32] * CAr[lane + 32]);
                           if (!lane) scal[3] = v; }
        else if (w == 4) { float v = warpSum(RPR[lane] + RPR[lane + 32]); if (!lane) scal[4] = v; }
        __syncthreads();
        TR = scal[0]; N2 = scal[1]; SRC2 = scal[2]; SPC = scal[3]; PR = scal[4];
    };

    auto applyK = [&](float d, float pp, int a) -> float {
        float Ra = RAd[a], Cb = CAd[b0], Rb = RBd[a], Cv = CBd[b0];
        return beta * d + rho * (Ra + Cb)
             - 0.5f * (pp * (TA - Ra - Cb + d) + (TB - Rb - Cv + pp * d));
    };

    float s1 = 0.f, s2 = 0.f, al1 = 0.f, al2 = 0.f, rhoz = 0.f;
    auto wood = [&]() {
        s1 = binv * PR + cRC * SPC + cT * TP * TR;
        s2 = b128i * TR;
        al1 = i11 * s1 + i12 * s2;
        al2 = i12 * s1 + i22 * s2;
        rhoz = binv * N2 + cRC * SRC2 + cT * TR * TR + al1 * s1 + al2 * s2;
    };

    for (int it = 0; it < 150; ++it) {
        if ((it & 7) == 0) {
            // refresh residual from scratch: publish X, strip sums, r = rhs - Kx
#pragma unroll
            for (int k = 0; k < 4; k++) X[off[k]] = x[k];
            __syncthreads();
            {
                float sv = 0.f, sp = 0.f;
#pragma unroll
                for (int j = 0; j < 4; j++) {
                    int o = rc * LD + g + 16 * j;
                    float m = X[o];
                    sv += m; sp += Pm[o] * m;
                }
                sv = dual16(sv); sp = dual16(sp);
                if (!g) { RAd[rc] = sv; RBd[rc] = sp; }
                float cv = 0.f, cp = 0.f;
#pragma unroll
                for (int j = 0; j < 4; j++) {
                    int o = (g + 16 * j) * LD + rc;
                    float m = X[o];
                    cv += m; cp += Pm[o] * m;
                }
                cv = dual16(cv); cp = dual16(cp);
                if (!g) { CAd[rc] = cv; CBd[rc] = cp; }
            }
            __syncthreads();
            TA = warpSum(RAd[lane] + RAd[lane + 32]);
            TB = warpSum(RBd[lane] + RBd[lane + 32]);
            float loc = 0.f;
#pragma unroll
            for (int k = 0; k < 4; k++) {
                float kx = applyK(x[k], p[k], aa[k]);
                float rhs = sigma * x[k] + p[k] + (rho * z1[k] - y1[k])
                          + (rho - y2c[b0]) + (rho - y2r[aa[k]]);
                r[k] = rhs - kx;
                Rr[off[k]] = r[k];
                loc += rhs * rhs;
            }
            loc = warpSum(loc);
            if (!lane) part[w] = loc;
            __syncthreads();
            float nr = warpSum(part[lane]);
            tol2 = fmaxf(nr * 1e-10f, 1e-28f);
            // refresh true row/col sums of x too (kill tracking drift)
            if (tid < 64) { RX[tid] = RAd[tid]; CX[tid] = CAd[tid]; }
            __syncthreads();
        }

        phaseR();

        if (N2 > tol2) {
            conv = 0;
            wood();
            float rho_s = rhoz;
            // d0 = B2^-1 r
#pragma unroll
            for (int k = 0; k < 4; k++) {
                float z = binv * r[k] + cRC * (RAr[aa[k]] + CAr[b0]) + cT * TR
                        + al1 * wp[k] + al2 * b128i;
                dreg[k] = z;
                Dd[off[k]] = z;
            }

            float prev = 3.4e38f;
            int stag = 0;
            for (int cg = 0; cg < 60; ++cg) {
                __syncthreads();          // Dd visible
                phaseD();                 // sums of d (2 barriers)
                // closed-form alpha
                float dq = beta * D2 + rho * SA2 - (TA * TB - SAB + PD2);
                if (!(dq > 0.f)) break;
                float alpha = rho_s / dq;
                // update x, r; track RX/CX incrementally
#pragma unroll
                for (int k = 0; k < 4; k++) {
                    float q = applyK(dreg[k], p[k], aa[k]);
                    x[k] += alpha * dreg[k];
                    r[k] -= alpha * q;
                    Rr[off[k]] = r[k];
                }
                if (tid < 64) {
                    RX[tid] += alpha * RAd[tid];
                    CX[tid] += alpha * CAd[tid];
                }
                __syncthreads();
                phaseR();                 // sums of r (2 barriers)
                if (N2 <= tol2) break;
                if (N2 >= 0.99f * prev) { if (++stag >= 3) break; }
                else stag = 0;
                prev = N2;
                wood();
                float bk = rhoz / rho_s;
                rho_s = rhoz;
#pragma unroll
                for (int k = 0; k < 4; k++) {
                    float z = binv * r[k] + cRC * (RAr[aa[k]] + CAr[b0]) + cT * TR
                            + al1 * wp[k] + al2 * b128i;
                    dreg[k] = z + bk * dreg[k];
                    Dd[off[k]] = dreg[k];
                }
            }
        } else {
            if (++conv >= 6) break;       // ADMM fixed point: x frozen, stop
        }

        // z/y updates + incremental residual (RX/CX tracked, no X publish)
#pragma unroll
        for (int k = 0; k < 4; k++) {
            float z1n = fminf(fmaxf(x[k] + y1[k] * (1.f / rho), 0.f), 1e6f);
            float rinc = sigma * (x[k] - xr[k]) + rho * (2.f * z1n - z1[k] - x[k])
                       - rho * (CX[b0] - 1.f) - rho * (RX[aa[k]] - 1.f);
            y1[k] += rho * (x[k] - z1n);
            z1[k] = z1n;
            r[k] += rinc;
            Rr[off[k]] = r[k];
            xr[k] = x[k];
        }
        if (tid < 64) {
            y2c[tid] += rho * (CX[tid] - 1.f);
            y2r[tid] += rho * (RX[tid] - 1.f);
        }
        __syncthreads();
    }

    // publish final X, then column-wise softmax: out[0][j][i] = softmax_i(200*clip)
#pragma unroll
    for (int k = 0; k < 4; k++) X[off[k]] = x[k];
    __syncthreads();
#pragma unroll
    for (int rr = 0; rr < 2; rr++) {
        int c = 2 * w + rr;
        float v1 = fminf(fmaxf(X[lane * LD + c], 0.f), 1.f);
        float v2 = fminf(fmaxf(X[(lane + 32) * LD + c], 0.f), 1.f);
        float mx = warpMax(fmaxf(v1, v2));
        float e1v = expf(200.f * (v1 - mx));
        float e2v = expf(200.f * (v2 - mx));
        float s = warpSum(e1v + e2v);
        out[c * 64 + lane] = e1v / s;
        out[c * 64 + lane + 32] = e2v / s;
    }
}

// ------------------------------------------------------------------------------------
extern "C" void kernel_launch(void* const* d_in, const int* in_sizes, int n_in,
                              void* d_out, int out_size) {
    const float* tra = (const float*)d_in[0];   // (64,512)
    const float* det = (const float*)d_in[1];   // (64,512)
    const float* iou = (const float*)d_in[2];   // (64,64)
    const float* W   = (const float*)d_in[3];   // (512,512)
    const float* b   = (const float*)d_in[4];   // (512,)
    float* out = (float*)d_out;                 // (1,64,64)

    const int SMEM_BYTES = (16640 + 16 * 64 + 32 + 8) * 4;  // 70816
    cudaFuncSetAttribute(k_admm, cudaFuncAttributeMaxDynamicSharedMemorySize, SMEM_BYTES);

    k_mp0<<<128, 1024>>>(tra, det, iou);
    k_m12<<<64, 1024>>>(tra, det);
    k_u<<<128, 512>>>(tra, det);
    k_egemm<<<2048, 1024>>>(W, b);
    k_enorm<<<128, 512>>>();
    k_P<<<128, 1024>>>();
    k_admm<<<1, 1024, SMEM_BYTES>>>(out);
}